// round 16
// baseline (speedup 1.0000x reference)
#include <cuda_runtime.h>
#include <cuda_fp16.h>
#include <cstdint>

// ============================================================================
// Tensor-core FIR via baseline mma.sync (HMMA), single-pass fp16, 2 CTA/SM.
// out[b,t] = sum_{i<kt} krev[i]*u[b,t+i],  krev[i] = kern[kt-1-i]
// Per tile: D[128 x 64] = U[128 x 256] * T^T,  T[n,k] = krev[k-n]
// A: ring of FIVE SMEM panels (128 rows x 64 cols fp16, stride 72) — the
//    write-target panel is never read by the current tile, so no WAR barrier.
// B: Toeplitz-dedup fragments (38 diagonals x 8B), rolling reuse across ks.
// One __syncthreads per tile. SMEM ~102 KB => 2 CTAs/SM.
// ============================================================================

#define TM_M 128
#define TM_N 64
#define TM_K 256
#define NTH  256
#define KS   16
#define NPANEL 5
#define NDIAG 38                                 // d = 2*ks - nc + 7 in [0,37]

#define A_STRIDE 72                              // 64 + 8 halves pad
#define A_PANEL_BYTES (TM_M * A_STRIDE * 2)      // 18432
#define OFF_A 0
#define OFF_B (NPANEL * A_PANEL_BYTES)           // 92160
#define B_BYTES (NDIAG * 32 * 8)                 // 9728
#define SMEM_TOTAL (OFF_B + B_BYTES)             // 101888

__device__ __forceinline__ uint32_t smem_addr(const void* p) {
    uint32_t a;
    asm("{ .reg .u64 t; cvta.to.shared.u64 t, %1; cvt.u32.u64 %0, t; }" : "=r"(a) : "l"(p));
    return a;
}
__device__ __forceinline__ void ldmA(uint32_t* r, uint32_t addr) {
    asm volatile("ldmatrix.sync.aligned.m8n8.x4.shared.b16 {%0,%1,%2,%3}, [%4];"
                 : "=r"(r[0]), "=r"(r[1]), "=r"(r[2]), "=r"(r[3]) : "r"(addr));
}
__device__ __forceinline__ void hmma(float* c, const uint32_t* a, uint32_t b0, uint32_t b1) {
    asm volatile(
        "mma.sync.aligned.m16n8k16.row.col.f32.f16.f16.f32 "
        "{%0,%1,%2,%3}, {%4,%5,%6,%7}, {%8,%9}, {%0,%1,%2,%3};"
        : "+f"(c[0]), "+f"(c[1]), "+f"(c[2]), "+f"(c[3])
        : "r"(a[0]), "r"(a[1]), "r"(a[2]), "r"(a[3]), "r"(b0), "r"(b1));
}
__device__ __forceinline__ uint32_t pkh(__half a, __half b) {
    return (uint32_t)__half_as_ushort(a) | ((uint32_t)__half_as_ushort(b) << 16);
}

__global__ __launch_bounds__(NTH, 2)
void fir_hmma_kernel(const float* __restrict__ u,
                     const float* __restrict__ kern,
                     float* __restrict__ out,
                     int t_out, int t_in, int b_total, int kt,
                     int n_ttiles, int tps)
{
    extern __shared__ char dsm[];
    const uint32_t sbase = smem_addr(dsm);
    const int tid  = threadIdx.x;
    const int wid  = tid >> 5;
    const int lane = tid & 31;
    const long long b0 = (long long)blockIdx.y * TM_M;
    const int tile0 = blockIdx.x * tps;
    const int ntile = min(tps, n_ttiles - tile0);
    const bool al4  = ((t_in & 3) == 0);

    // ---- build dedup B fragments (fp16), once per CTA ----
    for (int idx = tid; idx < NDIAG * 32; idx += NTH) {
        int l    = idx & 31;
        int dIdx = idx >> 5;
        int base = 8 * (dIdx - 7) + 2 * (l & 3) - (l >> 2);
        __half h[4];
        #pragma unroll
        for (int q = 0; q < 4; q++) {
            int i = base + (q & 1) + ((q >> 1) << 3);   // +0,+1,+8,+9
            float v = (i >= 0 && i < kt) ? kern[kt - 1 - i] : 0.0f;
            h[q] = __float2half_rn(v);
        }
        uint2 w;
        w.x = pkh(h[0], h[1]);
        w.y = pkh(h[2], h[3]);
        reinterpret_cast<uint2*>(dsm + OFF_B)[idx] = w;
    }

    // ---- panel staging: 128 rows x 16 float4; 8 float4 per thread ----
    float4 pf[8];
    auto ld_pf = [&](int c0) {
        #pragma unroll
        for (int q = 0; q < 8; q++) {
            int f   = tid + q * NTH;
            int row = f >> 4;
            int cl  = (f & 15) << 2;
            int g   = c0 + cl;
            long long b = b0 + row;
            float4 v = make_float4(0.f, 0.f, 0.f, 0.f);
            if (b < b_total) {
                const float* up = u + b * (long long)t_in + g;
                if (al4 && (g + 3 < t_in)) {
                    v = *(const float4*)up;
                } else {
                    if (g     < t_in) v.x = up[0];
                    if (g + 1 < t_in) v.y = up[1];
                    if (g + 2 < t_in) v.z = up[2];
                    if (g + 3 < t_in) v.w = up[3];
                }
            }
            pf[q] = v;
        }
    };
    auto st_pf = [&](int p) {
        char* pb = dsm + OFF_A + p * A_PANEL_BYTES;
        #pragma unroll
        for (int q = 0; q < 8; q++) {
            int f   = tid + q * NTH;
            int row = f >> 4;
            int cl  = (f & 15) << 2;
            uint2 hv;
            hv.x = pkh(__float2half_rn(pf[q].x), __float2half_rn(pf[q].y));
            hv.y = pkh(__float2half_rn(pf[q].z), __float2half_rn(pf[q].w));
            *reinterpret_cast<uint2*>(pb + (row * A_STRIDE + cl) * 2) = hv;
        }
    };

    // ---- warp tiling: 8 warps, 32 rows x 32 cols each ----
    const int mg  = wid >> 1;          // 0..3 -> rows mg*32
    const int ng  = wid & 1;           // 0..1 -> nc = ng*4 + j
    const int m0  = mg * 32;
    const uint32_t arow0 = sbase + OFF_A +
        (uint32_t)(((m0 + (lane & 7) + (lane & 8)) * A_STRIDE + ((lane & 16) ? 8 : 0)) * 2);
    const uint32_t arow1 = arow0 + (uint32_t)(16 * A_STRIDE * 2);

    const uint2* __restrict__ bt = reinterpret_cast<const uint2*>(dsm + OFF_B);
    const int d00 = 7 - 4 * ng;        // d for (ks=0, j=0)

    // ---- initial fill: panels 0..3 ----
    const int w0f = tile0 * TM_N;
    #pragma unroll 1
    for (int p = 0; p < 4; p++) { ld_pf(w0f + 64 * p); st_pf(p); }
    __syncthreads();

    int rs = 0;
    for (int s = 0; s < ntile; s++) {
        const int w0 = (tile0 + s) * TM_N;
        const bool havepf = (s + 1 < ntile);

        if (havepf) ld_pf(w0 + 256);   // LDGs overlap the MMA below

        // panel base offsets for this tile (ring mod 5)
        uint32_t pbase[4];
        #pragma unroll
        for (int q = 0; q < 4; q++) {
            int pp = rs + q; if (pp >= NPANEL) pp -= NPANEL;
            pbase[q] = (uint32_t)(pp * A_PANEL_BYTES);
        }

        float acc[2][4][4];
        #pragma unroll
        for (int f = 0; f < 2; f++)
            #pragma unroll
            for (int j = 0; j < 4; j++)
                #pragma unroll
                for (int q = 0; q < 4; q++) acc[f][j][q] = 0.0f;

        // rolling B fragments: bv[j] = fragD[d00 + 2*ks - j]
        uint2 bv[4];
        #pragma unroll
        for (int j = 0; j < 4; j++) bv[j] = bt[(d00 - j) * 32 + lane];

        #pragma unroll
        for (int ks = 0; ks < KS; ks++) {
            const uint32_t koff = pbase[ks >> 2] + (uint32_t)(((ks & 3) * 16) * 2);
            uint32_t a0[4], a1[4];
            ldmA(a0, arow0 + koff);
            ldmA(a1, arow1 + koff);
            #pragma unroll
            for (int j = 0; j < 4; j++) {
                hmma(acc[0][j], a0, bv[j].x, bv[j].y);
                hmma(acc[1][j], a1, bv[j].x, bv[j].y);
            }
            if (ks < KS - 1) {
                bv[2] = bv[0];
                bv[3] = bv[1];
                bv[0] = bt[(d00 + 2 * ks + 2) * 32 + lane];
                bv[1] = bt[(d00 + 2 * ks + 1) * 32 + lane];
            }
        }

        // ---- epilogue (global stores; no barrier needed) ----
        #pragma unroll
        for (int f = 0; f < 2; f++) {
            const long long r0 = b0 + m0 + f * 16 + (lane >> 2);
            #pragma unroll
            for (int j = 0; j < 4; j++) {
                int col = w0 + (ng * 4 + j) * 8 + (lane & 3) * 2;
                if (col < t_out) {
                    if (r0 < b_total)
                        *reinterpret_cast<float2*>(out + r0 * t_out + col) =
                            make_float2(acc[f][j][0], acc[f][j][1]);
                    if (r0 + 8 < b_total)
                        *reinterpret_cast<float2*>(out + (r0 + 8) * t_out + col) =
                            make_float2(acc[f][j][2], acc[f][j][3]);
                }
            }
        }

        // ---- stage next panel into the unread 5th slot; single barrier ----
        if (havepf) {
            int wp = rs + 4; if (wp >= NPANEL) wp -= NPANEL;
            st_pf(wp);
        }
        __syncthreads();               // staged panel visible for next tile
        rs = rs + 1; if (rs >= NPANEL) rs = 0;
    }
}

// Generic fallback for unexpected tap counts.
__global__ void fir_generic_kernel(const float* __restrict__ u,
                                   const float* __restrict__ kern,
                                   float* __restrict__ out,
                                   int t_out, int t_in, int kt)
{
    int t = blockIdx.x * blockDim.x + threadIdx.x;
    int row = blockIdx.y;
    if (t >= t_out) return;
    const float* urow = u + (long long)row * t_in;
    float acc = 0.0f;
    for (int i = 0; i < kt; i++)
        acc = fmaf(kern[kt - 1 - i], urow[t + i], acc);
    out[(long long)row * t_out + t] = acc;
}

extern "C" void kernel_launch(void* const* d_in, const int* in_sizes, int n_in,
                              void* d_out, int out_size)
{
    const float* u    = (const float*)d_in[0];
    const float* kern = (const float*)d_in[1];
    float* out        = (float*)d_out;

    const int kt      = in_sizes[1];
    const int b_total = (kt > 1) ? (in_sizes[0] - out_size) / (kt - 1) : 1;
    const int t_out   = out_size / b_total;
    const int t_in    = in_sizes[0] / b_total;

    if (kt >= 1 && kt <= TM_K - TM_N + 1) {
        cudaFuncSetAttribute(fir_hmma_kernel,
                             cudaFuncAttributeMaxDynamicSharedMemorySize, SMEM_TOTAL);
        const int n_btiles = (b_total + TM_M - 1) / TM_M;
        const int n_ttiles = (t_out + TM_N - 1) / TM_N;
        int strips_max = (148 * 2) / n_btiles; if (strips_max < 1) strips_max = 1;
        int tps    = (n_ttiles + strips_max - 1) / strips_max;
        int strips = (n_ttiles + tps - 1) / tps;
        dim3 grid(strips, n_btiles);
        fir_hmma_kernel<<<grid, NTH, SMEM_TOTAL>>>(u, kern, out, t_out, t_in,
                                                   b_total, kt, n_ttiles, tps);
    } else {
        dim3 grid((t_out + 255) / 256, b_total);
        fir_generic_kernel<<<grid, 256>>>(u, kern, out, t_out, t_in, kt);
    }
}